// round 4
// baseline (speedup 1.0000x reference)
#include <cuda_runtime.h>
#include <math.h>

#define BB   512
#define LL   10000
#define NCH  100          // chunks per sequence
#define LCH  100          // chunk length (NCH*LCH == LL)
#define NLAY 4

typedef unsigned long long u64;

// ---------- f32x2 packed helpers (Blackwell sm_103a) ----------
__device__ __forceinline__ u64 pk(float lo, float hi) {
    u64 r; asm("mov.b64 %0,{%1,%2};" : "=l"(r) : "f"(lo), "f"(hi)); return r;
}
__device__ __forceinline__ void upk(u64 v, float& lo, float& hi) {
    asm("mov.b64 {%0,%1},%2;" : "=f"(lo), "=f"(hi) : "l"(v));
}
__device__ __forceinline__ u64 fma2(u64 a, u64 b, u64 c) {
    u64 d; asm("fma.rn.f32x2 %0,%1,%2,%3;" : "=l"(d) : "l"(a), "l"(b), "l"(c)); return d;
}
__device__ __forceinline__ u64 mul2(u64 a, u64 b) {
    u64 d; asm("mul.rn.f32x2 %0,%1,%2;" : "=l"(d) : "l"(a), "l"(b)); return d;
}
__device__ __forceinline__ u64 add2(u64 a, u64 b) {
    u64 d; asm("add.rn.f32x2 %0,%1,%2;" : "=l"(d) : "l"(a), "l"(b)); return d;
}

// ---------- scratch (static device globals: no allocation allowed) ----------
__device__ float  g_u[BB * 2 * LL];              // (B,H,L) activations
__device__ float  g_y[BB * 2 * LL];              // (B,H,L) pre-GLU
__device__ float2 g_E[BB * NCH * 2 * 32];        // chunk-end local states
__device__ float2 g_carry[BB * NCH * 2 * 32];    // chunk carry-in states
__device__ float2 g_lam[NLAY * 2 * 32];          // lambda (re,im)
__device__ float2 g_cm[NLAY * 2 * 32];           // (2*Cn_re, -2*Cn_im)
__device__ float2 g_lamLc[NLAY * 2 * 32];        // lambda^LCH

// ---------- setup: per-mode constants (fp64 for phase accuracy) ----------
__global__ void k_setup(const float* __restrict__ log_dt,
                        const float* __restrict__ log_A_real,
                        const float* __restrict__ A_imag,
                        const float* __restrict__ C) {
    int i = threadIdx.x;                 // 0..255 = NLAY*2*32
    int n = i & 31, h = (i >> 5) & 1, l = i >> 6;
    int hn = (l * 2 + h) * 32 + n;
    double dt  = exp((double)log_dt[l * 2 + h]);
    double Are = -exp((double)log_A_real[hn]);
    double Aim = (double)A_imag[hn];
    double dre = Are * dt, dim = Aim * dt;
    double er  = exp(dre);
    double lre = er * cos(dim), lim = er * sin(dim);
    double erL = exp(dre * (double)LCH);
    double lLre = erL * cos(dim * (double)LCH);
    double lLim = erL * sin(dim * (double)LCH);
    double cr = (double)C[hn * 2 + 0], ci = (double)C[hn * 2 + 1];
    // Cn = Cc * (lambda - 1) / A
    double numr = lre - 1.0, numi = lim;
    double den = Are * Are + Aim * Aim;
    double qr = (numr * Are + numi * Aim) / den;
    double qi = (numi * Are - numr * Aim) / den;
    double cmr = 2.0 * (cr * qr - ci * qi);
    double cmi = 2.0 * (cr * qi + ci * qr);
    g_lam[hn]   = make_float2((float)lre, (float)lim);
    g_cm[hn]    = make_float2((float)cmr, (float)(-cmi));   // imag pre-negated
    g_lamLc[hn] = make_float2((float)lLre, (float)lLim);
}

// ---------- pre: u = x @ W1^T + b1, layout (B,H,L) ----------
__global__ void k_pre(const float* __restrict__ x,
                      const float* __restrict__ W1,
                      const float* __restrict__ b1) {
    int gid = blockIdx.x * blockDim.x + threadIdx.x;
    if (gid >= BB * LL) return;
    int b = gid / LL, t = gid - b * LL;
    const float* xp = x + (size_t)gid * 3;
    float x0 = xp[0], x1 = xp[1], x2 = xp[2];
    g_u[(size_t)(b * 2 + 0) * LL + t] =
        fmaf(W1[0], x0, fmaf(W1[1], x1, fmaf(W1[2], x2, b1[0])));
    g_u[(size_t)(b * 2 + 1) * LL + t] =
        fmaf(W1[3], x0, fmaf(W1[4], x1, fmaf(W1[5], x2, b1[1])));
}

// ---------- pass 1: local chunk recurrence (zero init) -> end states ----------
__global__ __launch_bounds__(128) void k_pass1(int layer) {
    int gid = blockIdx.x * 128 + threadIdx.x;    // B*NCH*2 threads
    int h  = gid & 1;
    int bc = gid >> 1;
    int c  = bc % NCH;
    int b  = bc / NCH;
    const float2* lam = g_lam + (layer * 2 + h) * 32;
    u64 lre[16], lim[16], sre[16], sim[16];
#pragma unroll
    for (int p = 0; p < 16; p++) {
        float2 a0 = lam[2 * p], a1 = lam[2 * p + 1];
        lre[p] = pk(a0.x, a1.x);
        lim[p] = pk(a0.y, a1.y);
        sre[p] = 0ULL;
        sim[p] = 0ULL;
    }
    const u64 NEG1 = pk(-1.f, -1.f);
    const float* up = g_u + (size_t)(b * 2 + h) * LL + c * LCH;
#pragma unroll 1
    for (int i = 0; i < LCH; i++) {
        float uv = __ldg(up + i);
        u64 ub = pk(uv, uv);
#pragma unroll
        for (int p = 0; p < 16; p++) {
            u64 t  = mul2(lim[p], sim[p]);
            u64 q  = fma2(lre[p], sre[p], ub);
            u64 nr = fma2(t, NEG1, q);                         // re' = lre*re - lim*im + u
            u64 ni = fma2(lim[p], sre[p], mul2(lre[p], sim[p])); // im' = lim*re + lre*im
            sre[p] = nr;
            sim[p] = ni;
        }
    }
    float2* Ep = g_E + (size_t)((b * NCH + c) * 2 + h) * 32;
#pragma unroll
    for (int p = 0; p < 16; p++) {
        float r0, r1, i0, i1;
        upk(sre[p], r0, r1);
        upk(sim[p], i0, i1);
        Ep[2 * p]     = make_float2(r0, i0);
        Ep[2 * p + 1] = make_float2(r1, i1);
    }
}

// ---------- pass 2: sequential chunk combine -> carry-in per chunk ----------
__global__ void k_pass2(int layer) {
    int tid = blockIdx.x * blockDim.x + threadIdx.x;   // B*2*32 threads
    if (tid >= BB * 2 * 32) return;
    int n = tid & 31, h = (tid >> 5) & 1, b = tid >> 6;
    float2 lL = g_lamLc[(layer * 2 + h) * 32 + n];
    float sr = 0.f, si = 0.f;
    for (int c = 0; c < NCH; c++) {
        size_t idx = (size_t)((b * NCH + c) * 2 + h) * 32 + n;
        g_carry[idx] = make_float2(sr, si);
        float2 e = g_E[idx];
        float nr = fmaf(lL.x, sr, fmaf(-lL.y, si, e.x));
        float ni = fmaf(lL.x, si, fmaf(lL.y, sr, e.y));
        sr = nr;
        si = ni;
    }
}

// ---------- pass 3: full recurrence with carry-in -> y (incl. D skip) ----------
__global__ __launch_bounds__(128) void k_pass3(int layer, const float* __restrict__ Dp) {
    int gid = blockIdx.x * 128 + threadIdx.x;    // B*NCH*2 threads
    int h  = gid & 1;
    int bc = gid >> 1;
    int c  = bc % NCH;
    int b  = bc / NCH;
    const float2* lam = g_lam + (layer * 2 + h) * 32;
    const float2* cmp = g_cm  + (layer * 2 + h) * 32;
    const float2* cyp = g_carry + (size_t)((b * NCH + c) * 2 + h) * 32;
    float Dh = __ldg(Dp + layer * 2 + h);
    u64 lre[16], lim[16], cre[16], nci[16], sre[16], sim[16];
#pragma unroll
    for (int p = 0; p < 16; p++) {
        float2 a0 = lam[2 * p], a1 = lam[2 * p + 1];
        lre[p] = pk(a0.x, a1.x);
        lim[p] = pk(a0.y, a1.y);
        float2 c0 = cmp[2 * p], c1 = cmp[2 * p + 1];
        cre[p] = pk(c0.x, c1.x);
        nci[p] = pk(c0.y, c1.y);                 // already negated imag
        float2 s0 = cyp[2 * p], s1 = cyp[2 * p + 1];
        sre[p] = pk(s0.x, s1.x);
        sim[p] = pk(s0.y, s1.y);
    }
    const u64 NEG1 = pk(-1.f, -1.f);
    const float* up = g_u + (size_t)(b * 2 + h) * LL + c * LCH;
    float*       yp = g_y + (size_t)(b * 2 + h) * LL + c * LCH;
#pragma unroll 1
    for (int i = 0; i < LCH; i++) {
        float uv = __ldg(up + i);
        u64 ub = pk(uv, uv);
        u64 a0 = 0ULL, a1 = 0ULL, a2 = 0ULL, a3 = 0ULL;
#pragma unroll
        for (int p = 0; p < 16; p++) {
            u64 t  = mul2(lim[p], sim[p]);
            u64 q  = fma2(lre[p], sre[p], ub);
            u64 nr = fma2(t, NEG1, q);
            u64 ni = fma2(lim[p], sre[p], mul2(lre[p], sim[p]));
            sre[p] = nr;
            sim[p] = ni;
            u64 ac = (p & 3) == 0 ? a0 : (p & 3) == 1 ? a1 : (p & 3) == 2 ? a2 : a3;
            ac = fma2(cre[p], nr, ac);
            ac = fma2(nci[p], ni, ac);
            if ((p & 3) == 0) a0 = ac; else if ((p & 3) == 1) a1 = ac;
            else if ((p & 3) == 2) a2 = ac; else a3 = ac;
        }
        u64 s = add2(add2(a0, a1), add2(a2, a3));
        float flo, fhi;
        upk(s, flo, fhi);
        yp[i] = flo + fhi + Dh * uv;
    }
}

// ---------- pass 4: GELU -> Wout (H->2H) -> GLU -> next u ----------
__device__ __forceinline__ float gelu_f(float x) {
    return 0.5f * x * (1.f + erff(x * 0.70710678118654752f));
}
__device__ __forceinline__ float sig_f(float x) {
    return 1.f / (1.f + __expf(-x));
}
__global__ void k_pass4(int layer, const float* __restrict__ Wout,
                        const float* __restrict__ bout) {
    int gid = blockIdx.x * blockDim.x + threadIdx.x;
    if (gid >= BB * LL) return;
    int b = gid / LL, t = gid - b * LL;
    float y0 = g_y[(size_t)(b * 2 + 0) * LL + t];
    float y1 = g_y[(size_t)(b * 2 + 1) * LL + t];
    float g0 = gelu_f(y0), g1 = gelu_f(y1);
    const float* W  = Wout + layer * 8;   // (2H, H) row-major
    const float* bo = bout + layer * 4;
    float z0 = fmaf(W[0], g0, fmaf(W[1], g1, bo[0]));
    float z1 = fmaf(W[2], g0, fmaf(W[3], g1, bo[1]));
    float z2 = fmaf(W[4], g0, fmaf(W[5], g1, bo[2]));
    float z3 = fmaf(W[6], g0, fmaf(W[7], g1, bo[3]));
    g_u[(size_t)(b * 2 + 0) * LL + t] = z0 * sig_f(z2);
    g_u[(size_t)(b * 2 + 1) * LL + t] = z1 * sig_f(z3);
}

// ---------- post: out = u^T @ W2^T + b2, layout (B,L,2) ----------
__global__ void k_post(const float* __restrict__ W2,
                       const float* __restrict__ b2,
                       float* __restrict__ out) {
    int gid = blockIdx.x * blockDim.x + threadIdx.x;
    if (gid >= BB * LL) return;
    int b = gid / LL, t = gid - b * LL;
    float u0 = g_u[(size_t)(b * 2 + 0) * LL + t];
    float u1 = g_u[(size_t)(b * 2 + 1) * LL + t];
    out[(size_t)gid * 2 + 0] = fmaf(W2[0], u0, fmaf(W2[1], u1, b2[0]));
    out[(size_t)gid * 2 + 1] = fmaf(W2[2], u0, fmaf(W2[3], u1, b2[1]));
}

extern "C" void kernel_launch(void* const* d_in, const int* in_sizes, int n_in,
                              void* d_out, int out_size) {
    (void)in_sizes; (void)n_in; (void)out_size;
    const float* x          = (const float*)d_in[0];
    const float* W1         = (const float*)d_in[1];
    const float* b1         = (const float*)d_in[2];
    const float* W2         = (const float*)d_in[3];
    const float* b2         = (const float*)d_in[4];
    const float* log_dt     = (const float*)d_in[5];
    const float* log_A_real = (const float*)d_in[6];
    const float* A_imag     = (const float*)d_in[7];
    const float* C          = (const float*)d_in[8];
    const float* D          = (const float*)d_in[9];
    const float* Wout       = (const float*)d_in[10];
    const float* bout       = (const float*)d_in[11];
    float* out = (float*)d_out;

    const int npt = BB * LL;                 // 5,120,000
    const int gpt = (npt + 255) / 256;       // 20,000 blocks
    const int g13 = (BB * NCH * 2) / 128;    // 800 blocks
    const int g2  = (BB * 2 * 32 + 255) / 256;

    k_setup<<<1, NLAY * 2 * 32>>>(log_dt, log_A_real, A_imag, C);
    k_pre<<<gpt, 256>>>(x, W1, b1);
    for (int l = 0; l < NLAY; l++) {
        k_pass1<<<g13, 128>>>(l);
        k_pass2<<<g2, 256>>>(l);
        k_pass3<<<g13, 128>>>(l, D);
        k_pass4<<<gpt, 256>>>(l, Wout, bout);
    }
    k_post<<<gpt, 256>>>(W2, b2, out);
}

// round 5
// speedup vs baseline: 1.1900x; 1.1900x over previous
#include <cuda_runtime.h>
#include <math.h>

#define BB   512
#define LL   10000
#define NCH  100          // chunks per sequence
#define LCH  100          // chunk length (NCH*LCH == LL)
#define NLAY 4

typedef unsigned long long u64;

// ---------- f32x2 packed helpers (Blackwell sm_103a) ----------
__device__ __forceinline__ u64 pk(float lo, float hi) {
    u64 r; asm("mov.b64 %0,{%1,%2};" : "=l"(r) : "f"(lo), "f"(hi)); return r;
}
__device__ __forceinline__ void upk(u64 v, float& lo, float& hi) {
    asm("mov.b64 {%0,%1},%2;" : "=f"(lo), "=f"(hi) : "l"(v));
}
__device__ __forceinline__ u64 fma2(u64 a, u64 b, u64 c) {
    u64 d; asm("fma.rn.f32x2 %0,%1,%2,%3;" : "=l"(d) : "l"(a), "l"(b), "l"(c)); return d;
}
__device__ __forceinline__ u64 mul2(u64 a, u64 b) {
    u64 d; asm("mul.rn.f32x2 %0,%1,%2;" : "=l"(d) : "l"(a), "l"(b)); return d;
}
__device__ __forceinline__ u64 add2(u64 a, u64 b) {
    u64 d; asm("add.rn.f32x2 %0,%1,%2;" : "=l"(d) : "l"(a), "l"(b)); return d;
}

// ---------- scratch (static device globals: no allocation allowed) ----------
__device__ float  g_u[BB * 2 * LL];              // (B,H,L) activations (updated in place)
__device__ float2 g_E[BB * NCH * 2 * 32];        // chunk-end local states
__device__ float2 g_carry[BB * NCH * 2 * 32];    // chunk carry-in states
__device__ float2 g_lam[NLAY * 2 * 32];          // lambda (re,im)
__device__ float2 g_cm[NLAY * 2 * 32];           // (2*Cn_re, -2*Cn_im)
__device__ float2 g_lamLc[NLAY * 2 * 32];        // lambda^LCH

// ---------- setup: per-mode constants (fp64 for phase accuracy) ----------
__global__ void k_setup(const float* __restrict__ log_dt,
                        const float* __restrict__ log_A_real,
                        const float* __restrict__ A_imag,
                        const float* __restrict__ C) {
    int i = threadIdx.x;                 // 0..255 = NLAY*2*32
    int n = i & 31, h = (i >> 5) & 1, l = i >> 6;
    int hn = (l * 2 + h) * 32 + n;
    double dt  = exp((double)log_dt[l * 2 + h]);
    double Are = -exp((double)log_A_real[hn]);
    double Aim = (double)A_imag[hn];
    double dre = Are * dt, dim = Aim * dt;
    double er  = exp(dre);
    double lre = er * cos(dim), lim = er * sin(dim);
    double erL = exp(dre * (double)LCH);
    double lLre = erL * cos(dim * (double)LCH);
    double lLim = erL * sin(dim * (double)LCH);
    double cr = (double)C[hn * 2 + 0], ci = (double)C[hn * 2 + 1];
    // Cn = Cc * (lambda - 1) / A
    double numr = lre - 1.0, numi = lim;
    double den = Are * Are + Aim * Aim;
    double qr = (numr * Are + numi * Aim) / den;
    double qi = (numi * Are - numr * Aim) / den;
    double cmr = 2.0 * (cr * qr - ci * qi);
    double cmi = 2.0 * (cr * qi + ci * qr);
    g_lam[hn]   = make_float2((float)lre, (float)lim);
    g_cm[hn]    = make_float2((float)cmr, (float)(-cmi));   // imag pre-negated
    g_lamLc[hn] = make_float2((float)lLre, (float)lLim);
}

// ---------- pre: u = x @ W1^T + b1, layout (B,H,L), 4 timesteps/thread ----------
__global__ void k_pre(const float* __restrict__ x,
                      const float* __restrict__ W1,
                      const float* __restrict__ b1) {
    int gid = blockIdx.x * blockDim.x + threadIdx.x;   // BB*LL/4 groups
    if (gid >= BB * (LL / 4)) return;
    int b = gid / (LL / 4), tg = gid - b * (LL / 4);
    int t = tg * 4;
    const float4* xp = (const float4*)(x + ((size_t)b * LL + t) * 3);
    float4 X0 = __ldg(xp), X1 = __ldg(xp + 1), X2 = __ldg(xp + 2);
    float w00 = W1[0], w01 = W1[1], w02 = W1[2], c0 = b1[0];
    float w10 = W1[3], w11 = W1[4], w12 = W1[5], c1 = b1[1];
    float xs[4][3] = {{X0.x, X0.y, X0.z}, {X0.w, X1.x, X1.y},
                      {X1.z, X1.w, X2.x}, {X2.y, X2.z, X2.w}};
    float4 u0, u1;
    float* p0 = &u0.x; float* p1 = &u1.x;
#pragma unroll
    for (int j = 0; j < 4; j++) {
        p0[j] = fmaf(w00, xs[j][0], fmaf(w01, xs[j][1], fmaf(w02, xs[j][2], c0)));
        p1[j] = fmaf(w10, xs[j][0], fmaf(w11, xs[j][1], fmaf(w12, xs[j][2], c1)));
    }
    *(float4*)(g_u + (size_t)(b * 2 + 0) * LL + t) = u0;
    *(float4*)(g_u + (size_t)(b * 2 + 1) * LL + t) = u1;
}

// ---------- pass 1: local chunk recurrence (zero init) -> end states ----------
// 4-op/mode recurrence using pre-negated lambda_im constant.
__global__ __launch_bounds__(128, 2) void k_pass1(int layer) {
    int gid = blockIdx.x * 128 + threadIdx.x;    // B*NCH*2 threads
    int h  = gid & 1;
    int bc = gid >> 1;
    int c  = bc % NCH;
    int b  = bc / NCH;
    const float2* lam = g_lam + (layer * 2 + h) * 32;
    u64 lre[16], lim[16], nli[16], sre[16], sim[16];
#pragma unroll
    for (int p = 0; p < 16; p++) {
        float2 a0 = lam[2 * p], a1 = lam[2 * p + 1];
        lre[p] = pk(a0.x, a1.x);
        lim[p] = pk(a0.y, a1.y);
        nli[p] = pk(-a0.y, -a1.y);
        sre[p] = 0ULL;
        sim[p] = 0ULL;
    }
    const float4* up4 = (const float4*)(g_u + (size_t)(b * 2 + h) * LL + c * LCH);
#pragma unroll 1
    for (int g = 0; g < LCH / 4; g++) {
        float4 uv = __ldg(up4 + g);
        const float us[4] = {uv.x, uv.y, uv.z, uv.w};
#pragma unroll
        for (int j = 0; j < 4; j++) {
            u64 ub = pk(us[j], us[j]);
#pragma unroll
            for (int p = 0; p < 16; p++) {
                u64 nr = fma2(nli[p], sim[p], fma2(lre[p], sre[p], ub));
                u64 ni = fma2(lim[p], sre[p], mul2(lre[p], sim[p]));
                sre[p] = nr;
                sim[p] = ni;
            }
        }
    }
    float2* Ep = g_E + (size_t)((b * NCH + c) * 2 + h) * 32;
#pragma unroll
    for (int p = 0; p < 16; p++) {
        float r0, r1, i0, i1;
        upk(sre[p], r0, r1);
        upk(sim[p], i0, i1);
        Ep[2 * p]     = make_float2(r0, i0);
        Ep[2 * p + 1] = make_float2(r1, i1);
    }
}

// ---------- pass 2: chunk combine with batched prefetch (MLP=10) ----------
__global__ void k_pass2(int layer) {
    int tid = blockIdx.x * 128 + threadIdx.x;   // B*2*32 threads
    if (tid >= BB * 2 * 32) return;
    int n = tid & 31, h = (tid >> 5) & 1, b = tid >> 6;
    float2 lL = g_lamLc[(layer * 2 + h) * 32 + n];
    float lr = lL.x, li = lL.y;
    size_t base = (size_t)b * NCH * 64 + (size_t)h * 32 + n;   // stride 64 per chunk
    float sr = 0.f, si = 0.f;
#pragma unroll 1
    for (int g = 0; g < NCH / 10; g++) {
        float2 e[10];
#pragma unroll
        for (int k = 0; k < 10; k++)
            e[k] = __ldg(&g_E[base + (size_t)(g * 10 + k) * 64]);
#pragma unroll
        for (int k = 0; k < 10; k++) {
            g_carry[base + (size_t)(g * 10 + k) * 64] = make_float2(sr, si);
            float nr = fmaf(lr, sr, fmaf(-li, si, e[k].x));
            float ni = fmaf(lr, si, fmaf(li, sr, e[k].y));
            sr = nr;
            si = ni;
        }
    }
}

// ---------- fused pass 3+4: recurrence -> y -> GELU -> Wout -> GLU -> u (in place) ----
__device__ __forceinline__ float gelu_f(float x) {
    return 0.5f * x * (1.f + erff(x * 0.70710678118654752f));
}
__device__ __forceinline__ float sig_f(float x) {
    return 1.f / (1.f + __expf(-x));
}
__global__ __launch_bounds__(128, 2) void k_fused3(int layer,
                                                   const float* __restrict__ Dp,
                                                   const float* __restrict__ Wout,
                                                   const float* __restrict__ bout) {
    int gid = blockIdx.x * 128 + threadIdx.x;    // B*NCH*2 threads
    int h  = gid & 1;
    int bc = gid >> 1;
    int c  = bc % NCH;
    int b  = bc / NCH;
    const float2* lam = g_lam + (layer * 2 + h) * 32;
    const float2* cmp = g_cm  + (layer * 2 + h) * 32;
    const float2* cyp = g_carry + (size_t)((b * NCH + c) * 2 + h) * 32;
    float Dh = __ldg(Dp + layer * 2 + h);
    // epilogue weights for this thread's output channel h and its gate 2+h
    const float* W  = Wout + layer * 8;   // (4 rows, 2 cols) row-major
    const float* bo = bout + layer * 4;
    int ho = 1 - h;
    float waS = W[h * 2 + h],       waO = W[h * 2 + ho],       ba = bo[h];
    float wgS = W[(2 + h) * 2 + h], wgO = W[(2 + h) * 2 + ho], bg = bo[2 + h];

    u64 lre[16], lim[16], cre[16], nci[16], sre[16], sim[16];
#pragma unroll
    for (int p = 0; p < 16; p++) {
        float2 a0 = lam[2 * p], a1 = lam[2 * p + 1];
        lre[p] = pk(a0.x, a1.x);
        lim[p] = pk(a0.y, a1.y);
        float2 c0 = cmp[2 * p], c1 = cmp[2 * p + 1];
        cre[p] = pk(c0.x, c1.x);
        nci[p] = pk(c0.y, c1.y);                 // already negated imag
        float2 s0 = cyp[2 * p], s1 = cyp[2 * p + 1];
        sre[p] = pk(s0.x, s1.x);
        sim[p] = pk(s0.y, s1.y);
    }
    const u64 NEG1 = pk(-1.f, -1.f);
    float* ubase = g_u + (size_t)(b * 2 + h) * LL + c * LCH;
#pragma unroll 1
    for (int g = 0; g < LCH / 4; g++) {
        float4 uv = __ldg((const float4*)ubase + g);
        const float us[4] = {uv.x, uv.y, uv.z, uv.w};
        float4 un;
        float* unp = &un.x;
#pragma unroll
        for (int j = 0; j < 4; j++) {
            u64 ub = pk(us[j], us[j]);
            u64 a0 = 0ULL, a1 = 0ULL, a2 = 0ULL, a3 = 0ULL;
#pragma unroll
            for (int p = 0; p < 16; p++) {
                u64 t  = mul2(lim[p], sim[p]);
                u64 q  = fma2(lre[p], sre[p], ub);
                u64 nr = fma2(t, NEG1, q);
                u64 ni = fma2(lim[p], sre[p], mul2(lre[p], sim[p]));
                sre[p] = nr;
                sim[p] = ni;
                u64 ac = (p & 3) == 0 ? a0 : (p & 3) == 1 ? a1 : (p & 3) == 2 ? a2 : a3;
                ac = fma2(cre[p], nr, ac);
                ac = fma2(nci[p], ni, ac);
                if ((p & 3) == 0) a0 = ac; else if ((p & 3) == 1) a1 = ac;
                else if ((p & 3) == 2) a2 = ac; else a3 = ac;
            }
            u64 s = add2(add2(a0, a1), add2(a2, a3));
            float flo, fhi;
            upk(s, flo, fhi);
            float y = flo + fhi + Dh * us[j];
            // fused GELU -> Wout -> GLU via pairwise shuffle (lanes 2k <-> 2k+1)
            float gown = gelu_f(y);
            float goth = __shfl_xor_sync(0xFFFFFFFFu, gown, 1);
            float za = fmaf(waS, gown, fmaf(waO, goth, ba));
            float zg = fmaf(wgS, gown, fmaf(wgO, goth, bg));
            unp[j] = za * sig_f(zg);
        }
        *((float4*)ubase + g) = un;   // in-place update of u for next layer
    }
}

// ---------- post: out = u^T @ W2^T + b2, layout (B,L,2), 4 timesteps/thread ----------
__global__ void k_post(const float* __restrict__ W2,
                       const float* __restrict__ b2,
                       float* __restrict__ out) {
    int gid = blockIdx.x * blockDim.x + threadIdx.x;
    if (gid >= BB * (LL / 4)) return;
    int b = gid / (LL / 4), tg = gid - b * (LL / 4);
    int t = tg * 4;
    float4 U0 = *(const float4*)(g_u + (size_t)(b * 2 + 0) * LL + t);
    float4 U1 = *(const float4*)(g_u + (size_t)(b * 2 + 1) * LL + t);
    const float* u0 = &U0.x; const float* u1 = &U1.x;
    float w00 = W2[0], w01 = W2[1], c0 = b2[0];
    float w10 = W2[2], w11 = W2[3], c1 = b2[1];
    float4 O0, O1;
    float* o = &O0.x;
#pragma unroll
    for (int j = 0; j < 2; j++) {
        o[2 * j + 0] = fmaf(w00, u0[j], fmaf(w01, u1[j], c0));
        o[2 * j + 1] = fmaf(w10, u0[j], fmaf(w11, u1[j], c1));
    }
    o = &O1.x;
#pragma unroll
    for (int j = 2; j < 4; j++) {
        o[2 * (j - 2) + 0] = fmaf(w00, u0[j], fmaf(w01, u1[j], c0));
        o[2 * (j - 2) + 1] = fmaf(w10, u0[j], fmaf(w11, u1[j], c1));
    }
    float4* op = (float4*)(out + ((size_t)b * LL + t) * 2);
    op[0] = O0;
    op[1] = O1;
}

extern "C" void kernel_launch(void* const* d_in, const int* in_sizes, int n_in,
                              void* d_out, int out_size) {
    (void)in_sizes; (void)n_in; (void)out_size;
    const float* x          = (const float*)d_in[0];
    const float* W1         = (const float*)d_in[1];
    const float* b1         = (const float*)d_in[2];
    const float* W2         = (const float*)d_in[3];
    const float* b2         = (const float*)d_in[4];
    const float* log_dt     = (const float*)d_in[5];
    const float* log_A_real = (const float*)d_in[6];
    const float* A_imag     = (const float*)d_in[7];
    const float* C          = (const float*)d_in[8];
    const float* D          = (const float*)d_in[9];
    const float* Wout       = (const float*)d_in[10];
    const float* bout       = (const float*)d_in[11];
    float* out = (float*)d_out;

    const int ngrp = BB * (LL / 4);          // 1,280,000 4-step groups
    const int gpt  = (ngrp + 255) / 256;     // 5000 blocks
    const int g13  = (BB * NCH * 2) / 128;   // 800 blocks
    const int g2   = (BB * 2 * 32) / 128;    // 256 blocks

    k_setup<<<1, NLAY * 2 * 32>>>(log_dt, log_A_real, A_imag, C);
    k_pre<<<gpt, 256>>>(x, W1, b1);
    for (int l = 0; l < NLAY; l++) {
        k_pass1<<<g13, 128>>>(l);
        k_pass2<<<g2, 128>>>(l);
        k_fused3<<<g13, 128>>>(l, D, Wout, bout);
    }
    k_post<<<gpt, 256>>>(W2, b2, out);
}